// round 2
// baseline (speedup 1.0000x reference)
#include <cuda_runtime.h>
#include <cstdint>

#define QNL 6

// Coefficient block:
// [0]      K (constant term incl. b2[1]-b2[0])
// [1..8]   circuit-1 coeffs for {cb, sb, ca, ca*cb, ca*sb, sa, sa*cb, sa*sb}
// [9..16]  circuit-2 coeffs, same order
// [17..28] angle affine maps: 4 rows of (w_x0, w_x1, bias) for a1,b1,a2,b2
__device__   float g_C[32];
__constant__ float c_C[32];

struct cpx { float x, y; };
__device__ __forceinline__ cpx cmul(cpx a, cpx b){ return cpx{a.x*b.x - a.y*b.y, a.x*b.y + a.y*b.x}; }
__device__ __forceinline__ cpx cadd(cpx a, cpx b){ return cpx{a.x + b.x, a.y + b.y}; }

// 32 threads: lanes 0-15 -> circuit 1, lanes 16-31 -> circuit 2.
__global__ void prelude_kernel(const float* __restrict__ qw1, const float* __restrict__ qw2,
                               const float* __restrict__ W1, const float* __restrict__ b1,
                               const float* __restrict__ W2, const float* __restrict__ b2)
{
    __shared__ cpx U[2][4][4];
    __shared__ cpx M[2][2][4][4];
    __shared__ float Kpart[2];

    int t = threadIdx.x;
    int c = t >> 4;          // circuit
    int e = t & 15;          // matrix entry
    int I = e >> 2, J = e & 3;
    const float* qw = c ? qw2 : qw1;

    U[c][I][J] = cpx{ (I == J) ? 1.0f : 0.0f, 0.0f };
    __syncwarp();

    // CNOT(q0->q1) permutes rows 2<->3; fold into which T-row we compute.
    int S  = (I < 2) ? I : (5 - I);
    int iS = S >> 1, jS = S & 1;

    for (int l = 0; l < QNL; l++){
        float s0, c0, s1, c1;
        __sincosf(qw[2*l + 0] * 0.5f, &s0, &c0);
        __sincosf(qw[2*l + 1] * 0.5f, &s1, &c1);
        cpx T = cpx{0.f, 0.f};
        #pragma unroll
        for (int K = 0; K < 4; K++){
            int kS = K >> 1, lS = K & 1;
            cpx r0 = (iS == kS) ? cpx{c0, 0.f} : cpx{0.f, -s0};
            cpx r1 = (jS == lS) ? cpx{c1, 0.f} : cpx{0.f, -s1};
            T = cadd(T, cmul(cmul(r0, r1), U[c][K][J]));
        }
        __syncwarp();
        U[c][I][J] = T;
        __syncwarp();
    }

    // M_m = U^dag D_m U, D0 = diag(1,1,-1,-1), D1 = diag(1,-1,1,-1)
    cpx m0 = cpx{0.f,0.f}, m1 = cpx{0.f,0.f};
    #pragma unroll
    for (int K = 0; K < 4; K++){
        cpx a = U[c][K][I];
        cpx b = U[c][K][J];
        cpx tK = cmul(cpx{a.x, -a.y}, b);
        float d0 = (K < 2)  ?  1.f : -1.f;
        float d1 = (K & 1)  ? -1.f :  1.f;
        m0.x += d0*tK.x; m0.y += d0*tK.y;
        m1.x += d1*tK.x; m1.y += d1*tK.y;
    }
    M[c][0][I][J] = m0;
    M[c][1][I][J] = m1;
    __syncwarp();

    if (e < 9){
        int alpha = e / 3, beta = e % 3;  // 0=I, 1=Z(cos), 2=Y(sin)
        float C0 = 0.f, C1 = 0.f;
        #pragma unroll
        for (int ra = 0; ra < 2; ra++){
            int ia = ra;
            int ka = (alpha == 2) ? 1 - ra : ra;
            cpx va = (alpha == 0) ? cpx{1.f, 0.f}
                   : (alpha == 1) ? cpx{ra ? -1.f : 1.f, 0.f}
                                  : cpx{0.f, ra ? 1.f : -1.f};
            #pragma unroll
            for (int rb = 0; rb < 2; rb++){
                int ib = rb;
                int kb = (beta == 2) ? 1 - rb : rb;
                cpx vb = (beta == 0) ? cpx{1.f, 0.f}
                       : (beta == 1) ? cpx{rb ? -1.f : 1.f, 0.f}
                                     : cpx{0.f, rb ? 1.f : -1.f};
                cpx v = cmul(va, vb);
                cpx e0 = M[c][0][2*ia + ib][2*ka + kb];
                cpx e1 = M[c][1][2*ia + ib][2*ka + kb];
                C0 += v.x*e0.x - v.y*e0.y;
                C1 += v.x*e1.x - v.y*e1.y;
            }
        }
        float w0 = W2[4 + 2*c + 0] - W2[2*c + 0];
        float w1 = W2[4 + 2*c + 1] - W2[2*c + 1];
        float g = 0.25f * (w0*C0 + w1*C1);
        if (e == 0) Kpart[c] = g;
        else        g_C[8*c + e] = g;
    }
    __syncwarp();
    if (t == 0) g_C[0] = (b2[1] - b2[0]) + Kpart[0] + Kpart[1];
    if (t < 12) g_C[17 + t] = ((t % 3) == 2) ? b1[t / 3] : W1[(t / 3) * 2 + (t % 3)];
}

// One batch element: returns (p0, p1). Balanced-tree evaluation, branch-free softmax.
__device__ __forceinline__ float2 eval_one(float x0, float x1){
    float a1 = fmaf(c_C[17], x0, fmaf(c_C[18], x1, c_C[19]));
    float b1 = fmaf(c_C[20], x0, fmaf(c_C[21], x1, c_C[22]));
    float a2 = fmaf(c_C[23], x0, fmaf(c_C[24], x1, c_C[25]));
    float b2 = fmaf(c_C[26], x0, fmaf(c_C[27], x1, c_C[28]));
    float sa1, ca1, sb1, cb1, sa2, ca2, sb2, cb2;
    __sincosf(a1, &sa1, &ca1);
    __sincosf(b1, &sb1, &cb1);
    __sincosf(a2, &sa2, &ca2);
    __sincosf(b2, &sb2, &cb2);

    // circuit 1: q1 + ca1*(...) + sa1*(...)
    float q1 = fmaf(c_C[1], cb1, fmaf(c_C[2],  sb1, c_C[0]));
    float p1 = ca1 * fmaf(c_C[4],  cb1, fmaf(c_C[5],  sb1, c_C[3]));
    float p2 = sa1 * fmaf(c_C[7],  cb1, fmaf(c_C[8],  sb1, c_C[6]));
    // circuit 2
    float q2 = fmaf(c_C[9], cb2, c_C[10] * sb2);
    float p3 = ca2 * fmaf(c_C[12], cb2, fmaf(c_C[13], sb2, c_C[11]));
    float p4 = sa2 * fmaf(c_C[15], cb2, fmaf(c_C[16], sb2, c_C[14]));

    float d = (q1 + p1) + (p2 + q2) + (p3 + p4);

    // softmax over (l0, l1) with d = l1 - l0:  p0 = 1/(1+e^d), p1 = e^d/(1+e^d)
    float ed = __expf(d);                       // |d| is small (few units); no overflow
    float r  = __fdividef(1.0f, 1.0f + ed);
    return make_float2(r, ed * r);
}

__global__ __launch_bounds__(256) void hybrid_main(const float4* __restrict__ xin,
                                                   float4* __restrict__ out, int half){
    int t = blockIdx.x * blockDim.x + threadIdx.x;
    if (t >= half) return;
    float4 v0 = __ldg(&xin[t]);
    float4 v1 = __ldg(&xin[t + half]);
    float2 r00 = eval_one(v0.x, v0.y);
    float2 r01 = eval_one(v0.z, v0.w);
    float2 r10 = eval_one(v1.x, v1.y);
    float2 r11 = eval_one(v1.z, v1.w);
    out[t]        = make_float4(r00.x, r00.y, r01.x, r01.y);
    out[t + half] = make_float4(r10.x, r10.y, r11.x, r11.y);
}

extern "C" void kernel_launch(void* const* d_in, const int* in_sizes, int n_in,
                              void* d_out, int out_size){
    const float* x   = (const float*)d_in[0];
    const float* W1  = (const float*)d_in[1];
    const float* b1  = (const float*)d_in[2];
    const float* qw1 = (const float*)d_in[3];
    const float* qw2 = (const float*)d_in[4];
    const float* W2  = (const float*)d_in[5];
    const float* b2  = (const float*)d_in[6];

    prelude_kernel<<<1, 32>>>(qw1, qw2, W1, b1, W2, b2);

    // Publish coefficients to constant memory (capturable D2D memcpy node).
    void* src = nullptr;
    cudaGetSymbolAddress(&src, g_C);
    cudaMemcpyToSymbolAsync(c_C, src, 32 * sizeof(float), 0, cudaMemcpyDeviceToDevice, 0);

    int nf4  = in_sizes[0] / 4;       // one float4 = 2 batch elements
    int half = nf4 / 2;               // each thread handles 2 float4s (4 elements)
    int grid = (half + 255) / 256;
    hybrid_main<<<grid, 256>>>((const float4*)x, (float4*)d_out, half);
}